// round 2
// baseline (speedup 1.0000x reference)
#include <cuda_runtime.h>
#include <math.h>

// Problem constants
#define NN 128      // memory slots
#define MM 64       // memory width
#define CTRL 512
#define NO 70       // M + 6 controller outputs
#define BMAX 16384
#define EPSF 1e-16f

// Scratch for controller outputs o = emb @ W^T + b  (B x 70).
// Referenced directly from device code -> no host-side symbol lookup needed.
__device__ float g_o[BMAX * NO];

// ---------------------------------------------------------------------------
// Kernel 1: tiled GEMM  O[B,70] = A[B,512] * W[70,512]^T + bias
// BM=128 rows, BN=72 (70 padded), BK=32, 256 threads, per-thread 4x9 tile.
// ---------------------------------------------------------------------------
__global__ __launch_bounds__(256) void ntm_gemm_kernel(
    const float* __restrict__ A,     // [B,512]
    const float* __restrict__ W,     // [70,512]
    const float* __restrict__ bias)  // [70]
{
    __shared__ float As[32][129];  // [kk][r], stride 129 -> conflict-free T-store
    __shared__ float Ws[32][73];   // [kk][c], stride 73  -> conflict-free store

    const int t = threadIdx.x;
    const int block_row = blockIdx.x * 128;
    const int tcol = t & 7;        // 8 col groups * 9 cols
    const int trow = t >> 3;       // 32 row groups * 4 rows

    float acc[4][9];
#pragma unroll
    for (int i = 0; i < 4; i++)
#pragma unroll
        for (int j = 0; j < 9; j++) acc[i][j] = 0.f;

    for (int k0 = 0; k0 < CTRL; k0 += 32) {
        // A tile: 128x32 -> As[kk][r]. Coalesced global (kk fast), banks (kk+r)%32.
#pragma unroll
        for (int i = 0; i < 16; i++) {
            int lin = t + 256 * i;
            int kk = lin & 31, r = lin >> 5;
            As[kk][r] = A[(size_t)(block_row + r) * CTRL + k0 + kk];
        }
        // W tile: 72x32 (rows 70,71 zero)
#pragma unroll
        for (int i = 0; i < 9; i++) {
            int lin = t + 256 * i;
            int kk = lin & 31, c = lin >> 5;  // c in [0,72)
            Ws[kk][c] = (c < NO) ? W[(size_t)c * CTRL + k0 + kk] : 0.f;
        }
        __syncthreads();

#pragma unroll
        for (int kk = 0; kk < 32; kk++) {
            float a0 = As[kk][trow * 4 + 0];
            float a1 = As[kk][trow * 4 + 1];
            float a2 = As[kk][trow * 4 + 2];
            float a3 = As[kk][trow * 4 + 3];
            float wv[9];
#pragma unroll
            for (int j = 0; j < 9; j++) wv[j] = Ws[kk][tcol * 9 + j];
#pragma unroll
            for (int j = 0; j < 9; j++) {
                acc[0][j] += a0 * wv[j];
                acc[1][j] += a1 * wv[j];
                acc[2][j] += a2 * wv[j];
                acc[3][j] += a3 * wv[j];
            }
        }
        __syncthreads();
    }

#pragma unroll
    for (int i = 0; i < 4; i++) {
        int row = block_row + trow * 4 + i;
#pragma unroll
        for (int j = 0; j < 9; j++) {
            int c = tcol * 9 + j;
            if (c < NO) g_o[(size_t)row * NO + c] = acc[i][j] + bias[c];
        }
    }
}

// ---------------------------------------------------------------------------
// Kernel 2: addressing + readout. One block per batch row, 128 threads.
// ---------------------------------------------------------------------------
__device__ __forceinline__ float softplus_f(float x) {
    return (x > 20.f) ? x : log1pf(expf(x));
}

__device__ __forceinline__ float warp_sum(float v) {
#pragma unroll
    for (int off = 16; off > 0; off >>= 1)
        v += __shfl_xor_sync(0xffffffffu, v, off);
    return v;
}
__device__ __forceinline__ float warp_max(float v) {
#pragma unroll
    for (int off = 16; off > 0; off >>= 1)
        v = fmaxf(v, __shfl_xor_sync(0xffffffffu, v, off));
    return v;
}

#define MS 65  // padded row stride: banks (65n+m)%32 = (n+m)%32 -> conflict-free

__global__ __launch_bounds__(128) void ntm_addr_kernel(
    const float* __restrict__ w_prev,  // [B,128]
    const float* __restrict__ memory,  // [B,128,64]
    float* __restrict__ out_r,         // [B,64]
    float* __restrict__ out_w)         // [B,128]
{
    __shared__ float mem_s[NN * MS];   // 128 x 65 floats (33280 B)
    __shared__ float ke[MM];           // k + EPS
    __shared__ float wg[NN];           // w_g, later reused for final w
    __shared__ float rpart[MM];
    __shared__ float red[8];
    __shared__ float scal[8];          // beta,g,s0,s1,s2,gamma,inv_knorm

    const int b = blockIdx.x;
    const int t = threadIdx.x;
    const int wid = t >> 5;
    const int lane = t & 31;

    const float* ob = g_o + (size_t)b * NO;

    // --- scalars + k ---
    if (t < MM) {
        ke[t] = ob[t] + EPSF;
    } else if (t == 64) {
        scal[0] = softplus_f(ob[MM]);                       // beta
    } else if (t == 65) {
        scal[1] = 1.f / (1.f + expf(-ob[MM + 1]));          // g
    } else if (t == 66) {
        float a = ob[MM + 2], bb = ob[MM + 3], c = ob[MM + 4];
        float mx = fmaxf(a, fmaxf(bb, c));
        float e0 = expf(a - mx), e1 = expf(bb - mx), e2 = expf(c - mx);
        float inv = 1.f / (e0 + e1 + e2);
        scal[2] = e0 * inv; scal[3] = e1 * inv; scal[4] = e2 * inv;   // s
    } else if (t == 67) {
        scal[5] = 1.f + softplus_f(ob[MM + 5]);             // gamma
    }

    // --- stage memory tile: coalesced float4 global reads, scalar smem stores ---
    const float4* mg = (const float4*)(memory + (size_t)b * NN * MM);
#pragma unroll
    for (int i = 0; i < 16; i++) {
        int lin = t + 128 * i;            // 0..2047 float4s
        float4 v = mg[lin];
        int n = lin >> 4, m4 = lin & 15;
        float* dst = mem_s + n * MS + m4 * 4;
        dst[0] = v.x; dst[1] = v.y; dst[2] = v.z; dst[3] = v.w;
    }
    __syncthreads();

    // --- k norm (warp 0) ---
    if (t < 32) {
        float v = ke[t] * ke[t] + ke[t + 32] * ke[t + 32];
        v = warp_sum(v);
        if (t == 0) scal[6] = rsqrtf(v);    // 1/||k||
    }
    __syncthreads();

    // --- cosine similarity: thread t owns row n = t ---
    const float* row = mem_s + t * MS;
    const float4* k4 = (const float4*)ke;
    float d = 0.f, q = 0.f;
#pragma unroll
    for (int i = 0; i < 16; i++) {
        float4 kv = k4[i];
        float x0 = row[4 * i + 0], x1 = row[4 * i + 1];
        float x2 = row[4 * i + 2], x3 = row[4 * i + 3];
        d += x0 * kv.x; q += x0 * x0;
        d += x1 * kv.y; q += x1 * x1;
        d += x2 * kv.z; q += x2 * x2;
        d += x3 * kv.w; q += x3 * x3;
    }

    const float beta = scal[0], g = scal[1];
    const float s0 = scal[2], s1 = scal[3], s2 = scal[4];
    const float gamma = scal[5];

    float cosv = d * rsqrtf(q) * scal[6];
    float z = beta * cosv;

    // --- softmax over 128 slots ---
    float mx = warp_max(z);
    if (lane == 0) red[wid] = mx;
    __syncthreads();
    mx = fmaxf(fmaxf(red[0], red[1]), fmaxf(red[2], red[3]));
    float e = expf(z - mx);
    float sw = warp_sum(e);
    if (lane == 0) red[4 + wid] = sw;
    __syncthreads();
    float inv_sum = 1.f / (red[4] + red[5] + red[6] + red[7]);
    float wc = e * inv_sum;

    // --- interpolate with previous weights ---
    float wp = w_prev[(size_t)b * NN + t];
    float wgv = g * wc + (1.f - g) * wp;
    wg[t] = wgv;
    __syncthreads();

    // --- circular shift ---
    float ws = s0 * wg[(t + NN - 1) & (NN - 1)]
             + s1 * wgv
             + s2 * wg[(t + 1) & (NN - 1)];

    // --- sharpen + normalize ---
    float wsh = powf(ws, gamma);
    float ssum = warp_sum(wsh);
    if (lane == 0) red[wid] = ssum;
    __syncthreads();            // also guarantees all wg reads above are done
    float wfin = wsh / ((red[0] + red[1] + red[2] + red[3]) + EPSF);
    out_w[(size_t)b * NN + t] = wfin;
    wg[t] = wfin;               // reuse for readout broadcast
    __syncthreads();

    // --- readout r[m] = sum_n w[n] * memory[n][m]; split n-range in halves ---
    const int mcol = t & 63;
    const int h = t >> 6;
    const float* base = mem_s + (h * 64) * MS + mcol;
    float acc = 0.f;
#pragma unroll 8
    for (int j = 0; j < 64; j++)
        acc += wg[h * 64 + j] * base[j * MS];
    if (h) rpart[mcol] = acc;
    __syncthreads();
    if (!h) out_r[(size_t)b * MM + mcol] = acc + rpart[mcol];
}

// ---------------------------------------------------------------------------
// Launcher — exactly two kernel launches, nothing else (graph-capture safe).
// ---------------------------------------------------------------------------
extern "C" void kernel_launch(void* const* d_in, const int* in_sizes, int n_in,
                              void* d_out, int out_size)
{
    const float* embeddings = (const float*)d_in[0];  // [B,512]
    const float* w_prev     = (const float*)d_in[1];  // [B,128]
    const float* memory     = (const float*)d_in[2];  // [B,128,64]
    const float* W          = (const float*)d_in[3];  // [70,512]
    const float* bias       = (const float*)d_in[4];  // [70]

    const int B = in_sizes[1] / NN;   // 16384

    float* out_r = (float*)d_out;           // [B,64]
    float* out_w = out_r + (size_t)B * MM;  // [B,128]

    ntm_gemm_kernel<<<B / 128, 256>>>(embeddings, W, bias);
    ntm_addr_kernel<<<B, 128>>>(w_prev, memory, out_r, out_w);
}